// round 2
// baseline (speedup 1.0000x reference)
#include <cuda_runtime.h>
#include <cstdint>

namespace {

constexpr int  kSamples = 16384;
constexpr int  kT       = 6;
constexpr int  kC       = 1024;
constexpr int  kHeads   = 8;
constexpr int  kHD      = 128;
constexpr long kRows    = (long)kSamples * kT;   // 98304
constexpr int  kSPC     = 21;                    // samples per CTA (126 rows, pad to 128)
constexpr int  kKC      = 32;                    // K-chunk
constexpr int  kChunks  = kC / kKC;              // 32
constexpr int  AS_STR   = 36;                    // E-chunk smem stride (floats)
constexpr int  BS_STR   = 264;                   // W-chunk smem stride (floats)
constexpr int  QK_STR   = 258;                   // QK smem stride (floats)
constexpr int  UNION_F  = 128 * QK_STR;          // 33024 floats (>= 2*(4608+8448)=26112)
constexpr int  SCORES_F = kSPC * 36;             // 756
constexpr int  GATE_F   = 128;
constexpr int  BIAS_F   = 256;
constexpr int  SMEM_F   = UNION_F + SCORES_F + GATE_F + BIAS_F;  // 34164
constexpr int  SMEM_BYTES = SMEM_F * 4;          // 136656

__device__ __forceinline__ uint32_t f2tf32(float x) {
  uint32_t r;
  asm("cvt.rna.tf32.f32 %0, %1;" : "=r"(r) : "f"(x));
  return r;
}

__device__ __forceinline__ void mma_tf32(float* d, const uint32_t* a, const uint32_t* b) {
  asm volatile(
      "mma.sync.aligned.m16n8k8.row.col.f32.tf32.tf32.f32 "
      "{%0,%1,%2,%3}, {%4,%5,%6,%7}, {%8,%9}, {%0,%1,%2,%3};\n"
      : "+f"(d[0]), "+f"(d[1]), "+f"(d[2]), "+f"(d[3])
      : "r"(a[0]), "r"(a[1]), "r"(a[2]), "r"(a[3]), "r"(b[0]), "r"(b[1]));
}

__device__ __forceinline__ void cpa16(float* dst, const float* src, int srcBytes) {
  uint32_t s = (uint32_t)__cvta_generic_to_shared(dst);
  asm volatile("cp.async.cg.shared.global [%0], [%1], 16, %2;\n"
               :: "r"(s), "l"(src), "r"(srcBytes));
}

}  // namespace

__global__ void __launch_bounds__(512, 1)
fused_attn_kernel(const float* __restrict__ emb, const float* __restrict__ ac,
                  const float* __restrict__ Wk,  const float* __restrict__ bk,
                  const float* __restrict__ Wq,  const float* __restrict__ bq,
                  const float* __restrict__ Wg,  const float* __restrict__ bg,
                  float* __restrict__ ctx, float* __restrict__ att) {
  extern __shared__ float sm[];
  float* AsBuf[2] = { sm,        sm + 13056 };
  float* BsBuf[2] = { sm + 4608, sm + 17664 };
  float* qk     = sm;                 // union-aliased with operand buffers
  float* sc     = sm + UNION_F;       // scores, then attention (in place)
  float* gate_s = sc + SCORES_F;
  float* bias_s = gate_s + GATE_F;

  const int tid  = threadIdx.x;
  const int lane = tid & 31;
  const int warp = tid >> 5;
  const int mw   = warp >> 2;    // 0..3
  const int nw   = warp & 3;     // 0..3
  const int lr   = lane >> 2;    // 0..7
  const int lc   = lane & 3;     // 0..3

  const int  sbase = blockIdx.x * kSPC;
  const long rbase = (long)sbase * kT;

  // ---- gate: g[s][j] = ac[s] . Wg[:,j] + bg[j]
  if (tid < kSPC * kT) {
    const int s = tid / kT, j = tid % kT;
    const int sg = sbase + s;
    float g = 0.f;
    if (sg < kSamples) {
      const float* ap = ac + (long)sg * 128;
      g = bg[j];
#pragma unroll 8
      for (int c = 0; c < 128; c++) g = fmaf(ap[c], Wg[c * 6 + j], g);
    }
    gate_s[tid] = g;
  }

  for (int h = 0; h < kHeads; h++) {
    if (tid < 256) bias_s[tid] = (tid < 128) ? bq[h * 128 + tid] : bk[h * 128 + tid - 128];

    float acc[2][8][4];
#pragma unroll
    for (int a0 = 0; a0 < 2; a0++)
#pragma unroll
      for (int a1 = 0; a1 < 8; a1++)
#pragma unroll
        for (int a2 = 0; a2 < 4; a2++) acc[a0][a1][a2] = 0.f;

    auto loadA = [&](int chunk, float* dst) {
      const int kc0 = chunk * kKC;
#pragma unroll
      for (int it = 0; it < 2; it++) {
        const int v = tid + it * 512;
        const int r = v >> 3, q = v & 7;     // 8 float4 per row of 32
        const long gr = rbase + r;
        const bool ok = gr < kRows;
        const float* g = emb + (ok ? gr : 0) * kC + kc0 + q * 4;
        cpa16(dst + r * AS_STR + q * 4, g, ok ? 16 : 0);
      }
    };
    auto loadB = [&](int chunk, float* dst) {
      const int kc0 = chunk * kKC;
#pragma unroll
      for (int it = 0; it < 4; it++) {
        const int v = tid + it * 512;
        const int k = v >> 6;                // 64 float4 per k-row (256 cols)
        const int col = (v & 63) * 4;
        const float* W = (col < 128) ? Wq : Wk;
        const int cc = (col < 128) ? col : col - 128;
        cpa16(dst + k * BS_STR + col, W + (long)(kc0 + k) * kC + h * kHD + cc, 16);
      }
    };

    loadA(0, AsBuf[0]); loadB(0, BsBuf[0]);
    asm volatile("cp.async.commit_group;\n" ::: "memory");
    loadA(1, AsBuf[1]); loadB(1, BsBuf[1]);
    asm volatile("cp.async.commit_group;\n" ::: "memory");

    for (int c = 0; c < kChunks; c++) {
      if (c == kChunks - 1) asm volatile("cp.async.wait_group 0;\n" ::: "memory");
      else                  asm volatile("cp.async.wait_group 1;\n" ::: "memory");
      __syncthreads();

      const float* A = AsBuf[c & 1];
      const float* B = BsBuf[c & 1];

#pragma unroll
      for (int ks = 0; ks < 4; ks++) {
        const int k0 = ks * 8;
        uint32_t af[2][4];
#pragma unroll
        for (int mt = 0; mt < 2; mt++) {
          const float* ap = A + (mw * 32 + mt * 16 + lr) * AS_STR + k0 + lc;
          af[mt][0] = f2tf32(ap[0]);
          af[mt][1] = f2tf32(ap[8 * AS_STR]);
          af[mt][2] = f2tf32(ap[4]);
          af[mt][3] = f2tf32(ap[8 * AS_STR + 4]);
        }
#pragma unroll
        for (int nt = 0; nt < 8; nt++) {
          const float* bp = B + (k0 + lc) * BS_STR + nw * 64 + nt * 8 + lr;
          uint32_t bf[2];
          bf[0] = f2tf32(bp[0]);
          bf[1] = f2tf32(bp[4 * BS_STR]);
          mma_tf32(acc[0][nt], af[0], bf);
          mma_tf32(acc[1][nt], af[1], bf);
        }
      }
      __syncthreads();
      if (c + 2 < kChunks) {
        loadA(c + 2, AsBuf[c & 1]);
        loadB(c + 2, BsBuf[c & 1]);
        asm volatile("cp.async.commit_group;\n" ::: "memory");
      }
    }

    // ---- dump Q|K tile (+bias) into union smem
#pragma unroll
    for (int mt = 0; mt < 2; mt++)
#pragma unroll
      for (int nt = 0; nt < 8; nt++) {
        const int r0 = mw * 32 + mt * 16 + lr;
        const int c0 = nw * 64 + nt * 8 + 2 * lc;
        qk[r0 * QK_STR + c0]           = acc[mt][nt][0] + bias_s[c0];
        qk[r0 * QK_STR + c0 + 1]       = acc[mt][nt][1] + bias_s[c0 + 1];
        qk[(r0 + 8) * QK_STR + c0]     = acc[mt][nt][2] + bias_s[c0];
        qk[(r0 + 8) * QK_STR + c0 + 1] = acc[mt][nt][3] + bias_s[c0 + 1];
      }
    __syncthreads();

    // ---- scores: one warp per sample, 128-dim dots via 4-elem/lane + butterfly
    const float kInvSqrt = 0.08838834764831845f;  // 1/sqrt(128)
    for (int s = warp; s < kSPC; s += 16) {
      const int sg = sbase + s;
      if (sg >= kSamples) continue;
      float qv[6][4], kv[6][4];
#pragma unroll
      for (int i = 0; i < 6; i++) {
        const float* qp = qk + (s * 6 + i) * QK_STR + lane;
#pragma unroll
        for (int t = 0; t < 4; t++) {
          qv[i][t] = qp[32 * t];
          kv[i][t] = qp[128 + 32 * t];
        }
      }
#pragma unroll
      for (int i = 0; i < 6; i++)
#pragma unroll
        for (int j = 0; j < 6; j++) {
          float p = qv[i][0] * kv[j][0] + qv[i][1] * kv[j][1]
                  + qv[i][2] * kv[j][2] + qv[i][3] * kv[j][3];
#pragma unroll
          for (int o = 16; o > 0; o >>= 1) p += __shfl_xor_sync(0xffffffffu, p, o);
          if (lane == 0) sc[s * 36 + i * 6 + j] = p;
        }
    }
    __syncthreads();

    // ---- gated softmax; write attention output; keep A in smem
    if (tid < kSPC * kT) {
      const int s = tid / 6, i = tid % 6;
      const int sg = sbase + s;
      if (sg < kSamples) {
        float l[6], mx = -1e30f;
#pragma unroll
        for (int j = 0; j < 6; j++) {
          l[j] = sc[s * 36 + i * 6 + j] * kInvSqrt * gate_s[s * 6 + j];
          mx = fmaxf(mx, l[j]);
        }
        float sum = 0.f;
#pragma unroll
        for (int j = 0; j < 6; j++) { l[j] = expf(l[j] - mx); sum += l[j]; }
        const float r = 1.f / sum;
        float* ao = att + (((long)sg * kHeads + h) * 6 + i) * 6;
#pragma unroll
        for (int j = 0; j < 6; j++) {
          const float a = l[j] * r;
          ao[j] = a;
          sc[s * 36 + i * 6 + j] = a;
        }
      }
    }
    __syncthreads();

    // ---- context: ctx[6s+i, h*128+c] = sum_j A[i][j] * E[6s+j, h*128+c]
    for (int idx = tid; idx < kSPC * kHD; idx += 512) {
      const int s = idx >> 7;
      const int cc = idx & 127;
      const int sg = sbase + s;
      if (sg >= kSamples) continue;
      const float* ep = emb + (long)sg * 6 * kC + h * kHD + cc;
      float e[6];
#pragma unroll
      for (int j = 0; j < 6; j++) e[j] = ep[(long)j * kC];
#pragma unroll
      for (int i = 0; i < 6; i++) {
        float v = 0.f;
#pragma unroll
        for (int j = 0; j < 6; j++) v = fmaf(sc[s * 36 + i * 6 + j], e[j], v);
        ctx[((long)sg * 6 + i) * kC + h * kHD + cc] = v;
      }
    }
    __syncthreads();
  }
}

extern "C" void kernel_launch(void* const* d_in, const int* in_sizes, int n_in,
                              void* d_out, int out_size) {
  (void)in_sizes; (void)n_in; (void)out_size;
  const float* emb = (const float*)d_in[0];
  const float* ac  = (const float*)d_in[1];
  const float* Wk  = (const float*)d_in[2];
  const float* bk  = (const float*)d_in[3];
  const float* Wq  = (const float*)d_in[4];
  const float* bq  = (const float*)d_in[5];
  const float* Wg  = (const float*)d_in[6];
  const float* bg  = (const float*)d_in[7];

  float* ctx = (float*)d_out;
  float* att = ctx + kRows * (long)kC;   // attention follows context

  cudaFuncSetAttribute(fused_attn_kernel,
                       cudaFuncAttributeMaxDynamicSharedMemorySize, SMEM_BYTES);
  const int grid = (kSamples + kSPC - 1) / kSPC;  // 781
  fused_attn_kernel<<<grid, 512, SMEM_BYTES>>>(emb, ac, Wk, bk, Wq, bq, Wg, bg, ctx, att);
}

// round 3
// speedup vs baseline: 1.0003x; 1.0003x over previous
#include <cuda_runtime.h>
#include <cstdint>

namespace {

constexpr int  kSamples = 16384;
constexpr int  kT       = 6;
constexpr int  kC       = 1024;
constexpr int  kHeads   = 8;
constexpr int  kHD      = 128;
constexpr long kRows    = (long)kSamples * kT;   // 98304
constexpr int  kSPC     = 21;                    // samples per CTA (126 rows, pad to 128)
constexpr int  kKC      = 32;                    // K-chunk
constexpr int  kChunks  = kC / kKC;              // 32
constexpr int  AS_STR   = 36;                    // E-chunk smem stride (floats)
constexpr int  BS_STR   = 264;                   // W-chunk smem stride (floats)
constexpr int  QK_STR   = 258;                   // QK smem stride (floats)
constexpr int  UNION_F  = 128 * QK_STR;          // 33024 floats (>= 2*(4608+8448)=26112)
constexpr int  SCORES_F = kSPC * 36;             // 756
constexpr int  GATE_F   = 128;
constexpr int  BIAS_F   = 256;
constexpr int  SMEM_F   = UNION_F + SCORES_F + GATE_F + BIAS_F;  // 34164
constexpr int  SMEM_BYTES = SMEM_F * 4;          // 136656

__device__ __forceinline__ uint32_t f2tf32(float x) {
  uint32_t r;
  asm("cvt.rna.tf32.f32 %0, %1;" : "=r"(r) : "f"(x));
  return r;
}

__device__ __forceinline__ void mma_tf32(float* d, const uint32_t* a, const uint32_t* b) {
  asm volatile(
      "mma.sync.aligned.m16n8k8.row.col.f32.tf32.tf32.f32 "
      "{%0,%1,%2,%3}, {%4,%5,%6,%7}, {%8,%9}, {%0,%1,%2,%3};\n"
      : "+f"(d[0]), "+f"(d[1]), "+f"(d[2]), "+f"(d[3])
      : "r"(a[0]), "r"(a[1]), "r"(a[2]), "r"(a[3]), "r"(b[0]), "r"(b[1]));
}

__device__ __forceinline__ void cpa16(float* dst, const float* src, int srcBytes) {
  uint32_t s = (uint32_t)__cvta_generic_to_shared(dst);
  asm volatile("cp.async.cg.shared.global [%0], [%1], 16, %2;\n"
               :: "r"(s), "l"(src), "r"(srcBytes));
}

}  // namespace

__global__ void __launch_bounds__(512, 1)
fused_attn_kernel(const float* __restrict__ emb, const float* __restrict__ ac,
                  const float* __restrict__ Wk,  const float* __restrict__ bk,
                  const float* __restrict__ Wq,  const float* __restrict__ bq,
                  const float* __restrict__ Wg,  const float* __restrict__ bg,
                  float* __restrict__ ctx, float* __restrict__ att) {
  extern __shared__ float sm[];
  float* AsBuf[2] = { sm,        sm + 13056 };
  float* BsBuf[2] = { sm + 4608, sm + 17664 };
  float* qk     = sm;                 // union-aliased with operand buffers
  float* sc     = sm + UNION_F;       // scores, then attention (in place)
  float* gate_s = sc + SCORES_F;
  float* bias_s = gate_s + GATE_F;

  const int tid  = threadIdx.x;
  const int lane = tid & 31;
  const int warp = tid >> 5;
  const int mw   = warp >> 2;    // 0..3
  const int nw   = warp & 3;     // 0..3
  const int lr   = lane >> 2;    // 0..7
  const int lc   = lane & 3;     // 0..3

  const int  sbase = blockIdx.x * kSPC;
  const long rbase = (long)sbase * kT;

  // ---- gate: g[s][j] = ac[s] . Wg[:,j] + bg[j]
  if (tid < kSPC * kT) {
    const int s = tid / kT, j = tid % kT;
    const int sg = sbase + s;
    float g = 0.f;
    if (sg < kSamples) {
      const float* ap = ac + (long)sg * 128;
      g = bg[j];
#pragma unroll 8
      for (int c = 0; c < 128; c++) g = fmaf(ap[c], Wg[c * 6 + j], g);
    }
    gate_s[tid] = g;
  }

  for (int h = 0; h < kHeads; h++) {
    if (tid < 256) bias_s[tid] = (tid < 128) ? bq[h * 128 + tid] : bk[h * 128 + tid - 128];

    float acc[2][8][4];
#pragma unroll
    for (int a0 = 0; a0 < 2; a0++)
#pragma unroll
      for (int a1 = 0; a1 < 8; a1++)
#pragma unroll
        for (int a2 = 0; a2 < 4; a2++) acc[a0][a1][a2] = 0.f;

    auto loadA = [&](int chunk, float* dst) {
      const int kc0 = chunk * kKC;
#pragma unroll
      for (int it = 0; it < 2; it++) {
        const int v = tid + it * 512;
        const int r = v >> 3, q = v & 7;     // 8 float4 per row of 32
        const long gr = rbase + r;
        const bool ok = gr < kRows;
        const float* g = emb + (ok ? gr : 0) * kC + kc0 + q * 4;
        cpa16(dst + r * AS_STR + q * 4, g, ok ? 16 : 0);
      }
    };
    auto loadB = [&](int chunk, float* dst) {
      const int kc0 = chunk * kKC;
#pragma unroll
      for (int it = 0; it < 4; it++) {
        const int v = tid + it * 512;
        const int k = v >> 6;                // 64 float4 per k-row (256 cols)
        const int col = (v & 63) * 4;
        const float* W = (col < 128) ? Wq : Wk;
        const int cc = (col < 128) ? col : col - 128;
        cpa16(dst + k * BS_STR + col, W + (long)(kc0 + k) * kC + h * kHD + cc, 16);
      }
    };

    loadA(0, AsBuf[0]); loadB(0, BsBuf[0]);
    asm volatile("cp.async.commit_group;\n" ::: "memory");
    loadA(1, AsBuf[1]); loadB(1, BsBuf[1]);
    asm volatile("cp.async.commit_group;\n" ::: "memory");

    for (int c = 0; c < kChunks; c++) {
      if (c == kChunks - 1) asm volatile("cp.async.wait_group 0;\n" ::: "memory");
      else                  asm volatile("cp.async.wait_group 1;\n" ::: "memory");
      __syncthreads();

      const float* A = AsBuf[c & 1];
      const float* B = BsBuf[c & 1];

#pragma unroll
      for (int ks = 0; ks < 4; ks++) {
        const int k0 = ks * 8;
        uint32_t af[2][4];
#pragma unroll
        for (int mt = 0; mt < 2; mt++) {
          const float* ap = A + (mw * 32 + mt * 16 + lr) * AS_STR + k0 + lc;
          af[mt][0] = f2tf32(ap[0]);
          af[mt][1] = f2tf32(ap[8 * AS_STR]);
          af[mt][2] = f2tf32(ap[4]);
          af[mt][3] = f2tf32(ap[8 * AS_STR + 4]);
        }
#pragma unroll
        for (int nt = 0; nt < 8; nt++) {
          const float* bp = B + (k0 + lc) * BS_STR + nw * 64 + nt * 8 + lr;
          uint32_t bf[2];
          bf[0] = f2tf32(bp[0]);
          bf[1] = f2tf32(bp[4 * BS_STR]);
          mma_tf32(acc[0][nt], af[0], bf);
          mma_tf32(acc[1][nt], af[1], bf);
        }
      }
      __syncthreads();
      if (c + 2 < kChunks) {
        loadA(c + 2, AsBuf[c & 1]);
        loadB(c + 2, BsBuf[c & 1]);
        asm volatile("cp.async.commit_group;\n" ::: "memory");
      }
    }

    // ---- dump Q|K tile (+bias) into union smem
#pragma unroll
    for (int mt = 0; mt < 2; mt++)
#pragma unroll
      for (int nt = 0; nt < 8; nt++) {
        const int r0 = mw * 32 + mt * 16 + lr;
        const int c0 = nw * 64 + nt * 8 + 2 * lc;
        qk[r0 * QK_STR + c0]           = acc[mt][nt][0] + bias_s[c0];
        qk[r0 * QK_STR + c0 + 1]       = acc[mt][nt][1] + bias_s[c0 + 1];
        qk[(r0 + 8) * QK_STR + c0]     = acc[mt][nt][2] + bias_s[c0];
        qk[(r0 + 8) * QK_STR + c0 + 1] = acc[mt][nt][3] + bias_s[c0 + 1];
      }
    __syncthreads();

    // ---- scores: one warp per sample, 128-dim dots via 4-elem/lane + butterfly
    const float kInvSqrt = 0.08838834764831845f;  // 1/sqrt(128)
    for (int s = warp; s < kSPC; s += 16) {
      const int sg = sbase + s;
      if (sg >= kSamples) continue;
      float qv[6][4], kv[6][4];
#pragma unroll
      for (int i = 0; i < 6; i++) {
        const float* qp = qk + (s * 6 + i) * QK_STR + lane;
#pragma unroll
        for (int t = 0; t < 4; t++) {
          qv[i][t] = qp[32 * t];
          kv[i][t] = qp[128 + 32 * t];
        }
      }
#pragma unroll
      for (int i = 0; i < 6; i++)
#pragma unroll
        for (int j = 0; j < 6; j++) {
          float p = qv[i][0] * kv[j][0] + qv[i][1] * kv[j][1]
                  + qv[i][2] * kv[j][2] + qv[i][3] * kv[j][3];
#pragma unroll
          for (int o = 16; o > 0; o >>= 1) p += __shfl_xor_sync(0xffffffffu, p, o);
          if (lane == 0) sc[s * 36 + i * 6 + j] = p;
        }
    }
    __syncthreads();

    // ---- gated softmax; write attention output; keep A in smem
    if (tid < kSPC * kT) {
      const int s = tid / 6, i = tid % 6;
      const int sg = sbase + s;
      if (sg < kSamples) {
        float l[6], mx = -1e30f;
#pragma unroll
        for (int j = 0; j < 6; j++) {
          l[j] = sc[s * 36 + i * 6 + j] * kInvSqrt * gate_s[s * 6 + j];
          mx = fmaxf(mx, l[j]);
        }
        float sum = 0.f;
#pragma unroll
        for (int j = 0; j < 6; j++) { l[j] = expf(l[j] - mx); sum += l[j]; }
        const float r = 1.f / sum;
        float* ao = att + (((long)sg * kHeads + h) * 6 + i) * 6;
#pragma unroll
        for (int j = 0; j < 6; j++) {
          const float a = l[j] * r;
          ao[j] = a;
          sc[s * 36 + i * 6 + j] = a;
        }
      }
    }
    __syncthreads();

    // ---- context: ctx[6s+i, h*128+c] = sum_j A[i][j] * E[6s+j, h*128+c]
    for (int idx = tid; idx < kSPC * kHD; idx += 512) {
      const int s = idx >> 7;
      const int cc = idx & 127;
      const int sg = sbase + s;
      if (sg >= kSamples) continue;
      const float* ep = emb + (long)sg * 6 * kC + h * kHD + cc;
      float e[6];
#pragma unroll
      for (int j = 0; j < 6; j++) e[j] = ep[(long)j * kC];
#pragma unroll
      for (int i = 0; i < 6; i++) {
        float v = 0.f;
#pragma unroll
        for (int j = 0; j < 6; j++) v = fmaf(sc[s * 36 + i * 6 + j], e[j], v);
        ctx[((long)sg * 6 + i) * kC + h * kHD + cc] = v;
      }
    }
    __syncthreads();
  }
}

extern "C" void kernel_launch(void* const* d_in, const int* in_sizes, int n_in,
                              void* d_out, int out_size) {
  (void)in_sizes; (void)n_in; (void)out_size;
  const float* emb = (const float*)d_in[0];
  const float* ac  = (const float*)d_in[1];
  const float* Wk  = (const float*)d_in[2];
  const float* bk  = (const float*)d_in[3];
  const float* Wq  = (const float*)d_in[4];
  const float* bq  = (const float*)d_in[5];
  const float* Wg  = (const float*)d_in[6];
  const float* bg  = (const float*)d_in[7];

  float* ctx = (float*)d_out;
  float* att = ctx + kRows * (long)kC;   // attention follows context

  cudaFuncSetAttribute(fused_attn_kernel,
                       cudaFuncAttributeMaxDynamicSharedMemorySize, SMEM_BYTES);
  const int grid = (kSamples + kSPC - 1) / kSPC;  // 781
  fused_attn_kernel<<<grid, 512, SMEM_BYTES>>>(emb, ac, Wk, bk, Wq, bq, Wg, bg, ctx, att);
}

// round 5
// speedup vs baseline: 2.0721x; 2.0715x over previous
#include <cuda_runtime.h>
#include <cuda_bf16.h>
#include <cstdint>

// ---------------- device scratch (globals — allowed) ----------------
__device__ __nv_bfloat16 g_Ebf[98304UL * 1024];   // E in bf16, row-major
__device__ __nv_bfloat16 g_Wt[8 * 256 * 1024];    // [head][n (Q0..127|K128..255)][k]

namespace {

constexpr int  kSamples = 16384;
constexpr long kRows    = 98304;               // 16384*6
constexpr int  CHUNKS   = 16;                  // K=1024 / 64
constexpr int  STAGE    = 49152;               // A 16KB + B 32KB
constexpr int  BOFF     = 16384;               // B within stage
constexpr uint32_t AUX  = 147456;              // after 3 stages
constexpr uint32_t BIASO= AUX;                 // 256 f32
constexpr uint32_t SCO  = AUX + 1024;          // 756 f32
constexpr uint32_t GATO = AUX + 4096;          // 128 f32
constexpr int  SMEM_TOTAL = 152576;
constexpr int  QKS = 257;                      // qk stride (floats); qk aliases stages

__device__ __forceinline__ uint32_t smem_u32(const void* p) {
  return (uint32_t)__cvta_generic_to_shared(p);
}
__device__ __forceinline__ void cpa16(uint32_t dst, const void* src, int sz) {
  asm volatile("cp.async.cg.shared.global [%0], [%1], 16, %2;\n"
               :: "r"(dst), "l"(src), "r"(sz));
}
__device__ __forceinline__ void ldsm4(uint32_t* r, uint32_t addr) {
  asm volatile("ldmatrix.sync.aligned.m8n8.x4.shared.b16 {%0,%1,%2,%3}, [%4];"
               : "=r"(r[0]), "=r"(r[1]), "=r"(r[2]), "=r"(r[3]) : "r"(addr));
}
__device__ __forceinline__ void mma_bf16(float* d, const uint32_t* a, const uint32_t* b) {
  asm volatile(
      "mma.sync.aligned.m16n8k16.row.col.f32.bf16.bf16.f32 "
      "{%0,%1,%2,%3}, {%4,%5,%6,%7}, {%8,%9}, {%0,%1,%2,%3};\n"
      : "+f"(d[0]), "+f"(d[1]), "+f"(d[2]), "+f"(d[3])
      : "r"(a[0]), "r"(a[1]), "r"(a[2]), "r"(a[3]), "r"(b[0]), "r"(b[1]));
}

}  // namespace

// ---------------- pre-pass kernels ----------------
__global__ void conv_e_kernel(const float* __restrict__ emb) {
  const long total = kRows * 1024 / 8;
  for (long i = blockIdx.x * 256L + threadIdx.x; i < total; i += (long)gridDim.x * 256) {
    const float4* s = (const float4*)emb + i * 2;
    float4 a = s[0], b = s[1];
    __nv_bfloat162* o = (__nv_bfloat162*)g_Ebf + i * 4;
    o[0] = __floats2bfloat162_rn(a.x, a.y);
    o[1] = __floats2bfloat162_rn(a.z, a.w);
    o[2] = __floats2bfloat162_rn(b.x, b.y);
    o[3] = __floats2bfloat162_rn(b.z, b.w);
  }
}

__global__ void conv_w_kernel(const float* __restrict__ Wq, const float* __restrict__ Wk) {
  const int idx = blockIdx.x * 256 + threadIdx.x;  // 262144 total
  const int h  = idx >> 15;
  const int n  = (idx >> 7) & 255;
  const int k0 = (idx & 127) * 8;
  const float* W = (n < 128) ? Wq : Wk;
  const int col = h * 128 + (n & 127);
  __nv_bfloat16* o = g_Wt + ((long)(h * 256 + n)) * 1024 + k0;
#pragma unroll
  for (int t = 0; t < 8; t++) o[t] = __float2bfloat16(W[(long)(k0 + t) * 1024 + col]);
}

// ---------------- main fused kernel ----------------
__global__ void __launch_bounds__(512, 1)
attn_main_kernel(const float* __restrict__ emb, const float* __restrict__ ac,
                 const float* __restrict__ bk, const float* __restrict__ bq,
                 const float* __restrict__ Wg, const float* __restrict__ bg,
                 float* __restrict__ ctx, float* __restrict__ att) {
  extern __shared__ char smc[];
  const uint32_t sb = smem_u32(smc);
  float* qk     = (float*)smc;             // 128 x 257 f32 (131,584B) aliases stages
  float* bia    = (float*)(smc + BIASO);
  float* sc     = (float*)(smc + SCO);
  float* gate_s = (float*)(smc + GATO);

  const int tid  = threadIdx.x;
  const int lane = tid & 31;
  const int warp = tid >> 5;
  const int mw   = warp >> 2;   // 0..3 (32-row band)
  const int nw   = warp & 3;    // 0..3 (64-col band)
  const int lr   = lane >> 2;   // 0..7
  const int lc   = lane & 3;    // 0..3

  const int  sbase = blockIdx.x * 21;
  const long rbase = (long)sbase * 6;

  // ---- gate: g[s][j] = ac[s] . Wg[:,j] + bg[j] (once per CTA)
  if (tid < 126) {
    const int s = tid / 6, j = tid % 6;
    const int sg = sbase + s;
    float g = 0.f;
    if (sg < kSamples) {
      const float* ap = ac + (long)sg * 128;
      g = bg[j];
#pragma unroll 8
      for (int c = 0; c < 128; c++) g = fmaf(ap[c], Wg[c * 6 + j], g);
    }
    gate_s[tid] = g;
  }

  // ---- per-lane ldmatrix address precompute (within-stage offsets)
  const int gq = lane >> 3, li = lane & 7;
  const int arow = mw * 32 + (gq & 1) * 8 + li;     // + mt*16
  const uint32_t aKb  = (uint32_t)((gq >> 1) * 16);
  const uint32_t aXor = (uint32_t)((arow & 7) << 4);
  const uint32_t aOff0 = (uint32_t)(arow * 128);
  const uint32_t aOff1 = aOff0 + 16 * 128;
  const int brow = nw * 64 + (gq >> 1) * 8 + li;    // + nt*16
  const uint32_t bKb  = (uint32_t)((gq & 1) * 16);
  const uint32_t bXor = (uint32_t)((brow & 7) << 4);
  const uint32_t bOffB = (uint32_t)(BOFF + brow * 128);

  auto loadA = [&](int c, int stage) {
    const int kc0 = c * 64;
#pragma unroll
    for (int it = 0; it < 2; it++) {
      const int v = tid + it * 512;         // 0..1023
      const int r = v >> 3, ch = v & 7;
      const long gr = rbase + r;
      const bool ok = gr < kRows;
      const uint32_t dst = sb + stage * STAGE + (uint32_t)(r * 128) +
                           (uint32_t)((ch * 16) ^ ((r & 7) << 4));
      cpa16(dst, g_Ebf + (ok ? gr : 0) * 1024 + kc0 + ch * 8, ok ? 16 : 0);
    }
  };
  auto loadB = [&](int c, int stage, int head) {
    const int kc0 = c * 64;
#pragma unroll
    for (int it = 0; it < 4; it++) {
      const int v = tid + it * 512;         // 0..2047
      const int n = v >> 3, ch = v & 7;
      const uint32_t dst = sb + stage * STAGE + BOFF + (uint32_t)(n * 128) +
                           (uint32_t)((ch * 16) ^ ((n & 7) << 4));
      cpa16(dst, g_Wt + (long)(head * 256 + n) * 1024 + kc0 + ch * 8, 16);
    }
  };

  const float kInvSqrt = 0.08838834764831845f;  // 1/sqrt(128)

  for (int head = 0; head < 8; head++) {
    if (tid < 256)
      bia[tid] = (tid < 128) ? bq[head * 128 + tid] : bk[head * 128 + tid - 128];

    float acc[2][8][4];
#pragma unroll
    for (int a0 = 0; a0 < 2; a0++)
#pragma unroll
      for (int a1 = 0; a1 < 8; a1++)
#pragma unroll
        for (int a2 = 0; a2 < 4; a2++) acc[a0][a1][a2] = 0.f;

    loadA(0, 0); loadB(0, 0, head);
    asm volatile("cp.async.commit_group;" ::: "memory");
    loadA(1, 1); loadB(1, 1, head);
    asm volatile("cp.async.commit_group;" ::: "memory");

    for (int c = 0; c < CHUNKS; c++) {
      if (c < CHUNKS - 1) asm volatile("cp.async.wait_group 1;" ::: "memory");
      else                asm volatile("cp.async.wait_group 0;" ::: "memory");
      __syncthreads();

      if (c + 2 < CHUNKS) {
        loadA(c + 2, (c + 2) % 3);
        loadB(c + 2, (c + 2) % 3, head);
        asm volatile("cp.async.commit_group;" ::: "memory");
      }

      const uint32_t stb = sb + (uint32_t)((c % 3) * STAGE);
#pragma unroll
      for (int ks = 0; ks < 4; ks++) {
        uint32_t a0[4], a1[4];
        const uint32_t akb = (uint32_t)(ks * 32) + aKb;
        ldsm4(a0, stb + aOff0 + (akb ^ aXor));
        ldsm4(a1, stb + aOff1 + (akb ^ aXor));
        const uint32_t bkb = (uint32_t)(ks * 32) + bKb;
#pragma unroll
        for (int nt = 0; nt < 4; nt++) {
          uint32_t b[4];
          ldsm4(b, stb + bOffB + (uint32_t)(nt * 16 * 128) + (bkb ^ bXor));
          mma_bf16(acc[0][nt * 2],     a0, b);
          mma_bf16(acc[0][nt * 2 + 1], a0, b + 2);
          mma_bf16(acc[1][nt * 2],     a1, b);
          mma_bf16(acc[1][nt * 2 + 1], a1, b + 2);
        }
      }
    }
    __syncthreads();   // all mma done; stage area now reusable as qk

    // ---- dump Q|K tile (+bias) into union smem
#pragma unroll
    for (int mt = 0; mt < 2; mt++)
#pragma unroll
      for (int nt = 0; nt < 8; nt++) {
        const int r0 = mw * 32 + mt * 16 + lr;
        const int c0 = nw * 64 + nt * 8 + 2 * lc;
        qk[r0 * QKS + c0]           = acc[mt][nt][0] + bia[c0];
        qk[r0 * QKS + c0 + 1]       = acc[mt][nt][1] + bia[c0 + 1];
        qk[(r0 + 8) * QKS + c0]     = acc[mt][nt][2] + bia[c0];
        qk[(r0 + 8) * QKS + c0 + 1] = acc[mt][nt][3] + bia[c0 + 1];
      }
    __syncthreads();

    // ---- scores: one warp per sample
    for (int s = warp; s < 21; s += 16) {
      const int sg = sbase + s;
      if (sg >= kSamples) continue;
      float qv[6][4], kv[6][4];
#pragma unroll
      for (int i = 0; i < 6; i++) {
        const float* qp = qk + (s * 6 + i) * QKS + lane;
#pragma unroll
        for (int t = 0; t < 4; t++) {
          qv[i][t] = qp[32 * t];
          kv[i][t] = qp[128 + 32 * t];
        }
      }
#pragma unroll
      for (int i = 0; i < 6; i++)
#pragma unroll
        for (int j = 0; j < 6; j++) {
          float p = qv[i][0] * kv[j][0] + qv[i][1] * kv[j][1]
                  + qv[i][2] * kv[j][2] + qv[i][3] * kv[j][3];
#pragma unroll
          for (int o = 16; o > 0; o >>= 1) p += __shfl_xor_sync(0xffffffffu, p, o);
          if (lane == 0) sc[s * 36 + i * 6 + j] = p;
        }
    }
    __syncthreads();

    // ---- gated softmax; write attention; keep A in smem
    if (tid < 126) {
      const int s = tid / 6, i = tid % 6;
      const int sg = sbase + s;
      if (sg < kSamples) {
        float l[6], mx = -1e30f;
#pragma unroll
        for (int j = 0; j < 6; j++) {
          l[j] = sc[s * 36 + i * 6 + j] * kInvSqrt * gate_s[s * 6 + j];
          mx = fmaxf(mx, l[j]);
        }
        float sum = 0.f;
#pragma unroll
        for (int j = 0; j < 6; j++) { l[j] = expf(l[j] - mx); sum += l[j]; }
        const float rcp = 1.f / sum;
        float* ao = att + (((long)sg * 8 + head) * 6 + i) * 6;
#pragma unroll
        for (int j = 0; j < 6; j++) {
          const float a = l[j] * rcp;
          ao[j] = a;
          sc[s * 36 + i * 6 + j] = a;
        }
      }
    }
    __syncthreads();

    // ---- context: ctx[6s+i, head*128+cc] = sum_j A[i][j] * E[6s+j, head*128+cc]
    for (int idx = tid; idx < 21 * 128; idx += 512) {
      const int s = idx >> 7;
      const int cc = idx & 127;
      const int sg = sbase + s;
      if (sg >= kSamples) continue;
      const float* ep = emb + (long)sg * 6 * 1024 + head * 128 + cc;
      float e[6];
#pragma unroll
      for (int j = 0; j < 6; j++) e[j] = ep[(long)j * 1024];
#pragma unroll
      for (int i = 0; i < 6; i++) {
        float v = 0.f;
#pragma unroll
        for (int j = 0; j < 6; j++) v = fmaf(sc[s * 36 + i * 6 + j], e[j], v);
        ctx[((long)sg * 6 + i) * 1024 + head * 128 + cc] = v;
      }
    }
    __syncthreads();
  }
}

extern "C" void kernel_launch(void* const* d_in, const int* in_sizes, int n_in,
                              void* d_out, int out_size) {
  (void)in_sizes; (void)n_in; (void)out_size;
  const float* emb = (const float*)d_in[0];
  const float* ac  = (const float*)d_in[1];
  const float* Wk  = (const float*)d_in[2];
  const float* bk  = (const float*)d_in[3];
  const float* Wq  = (const float*)d_in[4];
  const float* bq  = (const float*)d_in[5];
  const float* Wg  = (const float*)d_in[6];
  const float* bg  = (const float*)d_in[7];

  float* ctx = (float*)d_out;
  float* att = ctx + kRows * 1024L;

  conv_e_kernel<<<8192, 256>>>(emb);
  conv_w_kernel<<<1024, 256>>>(Wq, Wk);

  cudaFuncSetAttribute(attn_main_kernel,
                       cudaFuncAttributeMaxDynamicSharedMemorySize, SMEM_TOTAL);
  attn_main_kernel<<<781, 512, SMEM_TOTAL>>>(emb, ac, bk, bq, Wg, bg, ctx, att);
}